// round 9
// baseline (speedup 1.0000x reference)
#include <cuda_runtime.h>
#include <cuda_fp16.h>
#include <cstdint>

#define NPOS    2048
#define CIN     256
#define COUT    256
#define BATCH   64
#define TI      2
#define KC      16
#define NCHUNK  (CIN / KC)     // 16
#define THREADS 512
#define NSTAGE  4

#define XSTRIDE 48
#define XT_BYTES    (BATCH * XSTRIDE)           // 3072
#define STAGE_BYTES (TI * XT_BYTES)             // 6144
#define XOFF(s, p) ((s) * STAGE_BYTES + (p) * XT_BYTES)

// scratch: xt[kc(16)][ipair(1024)][pos(2)][b(64)][kslot(16)] f16 = 64Mi halfwords
__device__ __half g_xt[NCHUNK * (NPOS / TI) * TI * BATCH * KC];

static __device__ __forceinline__ uint32_t smem_u32(const void* p) {
    uint32_t a;
    asm("{ .reg .u64 t; cvta.to.shared.u64 t, %1; cvt.u32.u64 %0, t; }"
        : "=r"(a) : "l"(p));
    return a;
}

static __device__ __forceinline__ uint32_t h2pack(float lo, float hi) {
    __half2 h = __floats2half2_rn(lo, hi);
    return *reinterpret_cast<uint32_t*>(&h);
}

static __device__ __forceinline__ void sts64(uint32_t addr, uint32_t a, uint32_t b) {
    asm volatile("st.shared.v2.u32 [%0], {%1, %2};" :: "r"(addr), "r"(a), "r"(b) : "memory");
}

static __device__ __forceinline__ void ldsm4(uint32_t addr, uint32_t r[4]) {
    asm volatile("ldmatrix.sync.aligned.m8n8.x4.shared.b16 {%0,%1,%2,%3}, [%4];"
                 : "=r"(r[0]), "=r"(r[1]), "=r"(r[2]), "=r"(r[3]) : "r"(addr));
}

static __device__ __forceinline__ void mma16816(float d[4], const uint32_t a[4],
                                                const uint32_t b0, const uint32_t b1) {
    asm volatile(
        "mma.sync.aligned.m16n8k16.row.col.f32.f16.f16.f32 "
        "{%0,%1,%2,%3}, {%4,%5,%6,%7}, {%8,%9}, {%0,%1,%2,%3};"
        : "+f"(d[0]), "+f"(d[1]), "+f"(d[2]), "+f"(d[3])
        : "r"(a[0]), "r"(a[1]), "r"(a[2]), "r"(a[3]), "r"(b0), "r"(b1));
}

// k permutation: physical k (within chunk) 4c+d -> halfword slot
static __device__ __forceinline__ int kslot(int kappa) {
    const int c = kappa >> 2, d = kappa & 3;
    return (d < 2) ? (2 * c + d) : (2 * c + d + 6);
}

// ============================================================================
// Pass 1: x[b][c][i] f32  ->  xt[kc][i>>1][i&1][b][kslot(c&15)] f16
// Grid: 64 b * 64 i-groups; 256 threads.
// ============================================================================
__global__ __launch_bounds__(256)
void x_transpose_kernel(const float* __restrict__ x) {
    __shared__ __half st[CIN][34];          // [c][i_local], padded

    const int b  = blockIdx.x >> 6;
    const int i0 = (blockIdx.x & 63) * 32;
    const int tid  = threadIdx.x;
    const int w    = tid >> 5;
    const int lane = tid & 31;

    // Phase A: coalesced read along i, convert, stage
    const float* xp = x + ((size_t)b * CIN) * NPOS + i0 + lane;
#pragma unroll 4
    for (int cc = 0; cc < 32; ++cc) {
        const int c = w * 32 + cc;
        st[c][lane] = __float2half_rn(xp[(size_t)c * NPOS]);
    }
    __syncthreads();

    // Phase B: each thread emits one (i, kc) 32B row (slot-permuted)
    const int il = tid & 31;               // i_local
    const int i  = i0 + il;
#pragma unroll
    for (int kh = 0; kh < 2; ++kh) {
        const int kc = kh * 8 + (tid >> 5);
        __half buf[KC];
#pragma unroll
        for (int kap = 0; kap < KC; ++kap)
            buf[kslot(kap)] = st[kc * KC + kap][il];
        // dst halfword index: ((kc*1024 + i>>1)*2 + (i&1))*2048... = (kc*2048 + i)*1024? No:
        // ((kc*(NPOS/TI) + (i>>1)) * TI + (i&1)) * (BATCH*KC) + b*KC
        const size_t dst = ((size_t)(kc * (NPOS / TI) + (i >> 1)) * TI + (i & 1))
                               * (BATCH * KC) + b * KC;
        *reinterpret_cast<uint4*>(&g_xt[dst]) = *reinterpret_cast<const uint4*>(&buf[0]);
        *reinterpret_cast<uint4*>(&g_xt[dst + 8]) = *reinterpret_cast<const uint4*>(&buf[8]);
    }
}

// ============================================================================
// Main GEMM kernel (round-6 structure; x path replaced by xt loads)
// ============================================================================
__global__ __launch_bounds__(THREADS, 1)
void fc_hmma7_kernel(const float* __restrict__ W,     // [N_POS, C_OUT, C_IN]
                     const float* __restrict__ bias,  // [N_POS, C_OUT]
                     float* __restrict__ out)         // [B, C_OUT, N_POS]
{
    __shared__ __align__(128) char xs[NSTAGE * STAGE_BYTES];   // 24576 B
    const uint32_t sb = smem_u32(xs);

    const int tid  = threadIdx.x;
    const int wid  = tid >> 5;
    const int lane = tid & 31;
    const int i0   = blockIdx.x * TI;

    const int row0 = lane >> 2;
    const int kq   = (lane & 3) * 4;

    const float* Wp[TI];
#pragma unroll
    for (int p = 0; p < TI; ++p)
        Wp[p] = W + ((size_t)(i0 + p) * COUT + wid * 16 + row0) * CIN;

    // xt chunk base for this CTA (halfword units); thread reads 8B at +tid*4
    const __half* xtb = g_xt + (size_t)blockIdx.x * (TI * BATCH * KC) + tid * 4;
    // per-chunk advance = 1024 ipairs * 2048 halfwords
    const size_t xstep = (size_t)(NPOS / TI) * (TI * BATCH * KC);

    // smem target for this thread's 8B: pos = tid>>8, b = (tid>>2)&63, part = tid&3
    const uint32_t sdst = (uint32_t)XOFF(0, tid >> 8)
                        + (uint32_t)(((tid >> 2) & 63) * XSTRIDE + (tid & 3) * 8);

    float acc[TI][8][4];
#pragma unroll
    for (int p = 0; p < TI; ++p)
#pragma unroll
        for (int n = 0; n < 8; ++n)
#pragma unroll
            for (int c = 0; c < 4; ++c) acc[p][n][c] = 0.0f;

    const int bj = lane >> 3, br = lane & 7;
    const uint32_t b_off = (uint32_t)(((bj & 2) * 4 + br) * XSTRIDE + ((bj & 1) << 4));

    float4 q[TI][2];       // W quads, depth 1
    uint2  xr[2];          // xt, depth 2 (one 8B unit per chunk set)

    auto ldg_w = [&](int kc) {
        const int kb = kc * KC + kq;
#pragma unroll
        for (int p = 0; p < TI; ++p) {
            q[p][0] = *reinterpret_cast<const float4*>(Wp[p] + kb);
            q[p][1] = *reinterpret_cast<const float4*>(Wp[p] + 8 * CIN + kb);
        }
    };

    auto ldg_x = [&](int kc, int set) {
        xr[set] = *reinterpret_cast<const uint2*>(xtb + (size_t)kc * xstep);
    };

    auto sts_x = [&](int s, int set) {
        sts64(sb + sdst + (uint32_t)(s * STAGE_BYTES), xr[set].x, xr[set].y);
    };

    uint32_t ah[TI][4], al[TI][4];
    auto cvt_w = [&]() {
#pragma unroll
        for (int p = 0; p < TI; ++p) {
#pragma unroll
            for (int r = 0; r < 2; ++r) {
                const float4 v = q[p][r];
                const uint32_t h02 = h2pack(v.x, v.y);
                const uint32_t h13 = h2pack(v.z, v.w);
                __half2 hh02 = *reinterpret_cast<const __half2*>(&h02);
                __half2 hh13 = *reinterpret_cast<const __half2*>(&h13);
                ah[p][r]     = h02;
                ah[p][r + 2] = h13;
                al[p][r]     = h2pack(v.x - __low2float(hh02), v.y - __high2float(hh02));
                al[p][r + 2] = h2pack(v.z - __low2float(hh13), v.w - __high2float(hh13));
            }
        }
    };

    auto compute = [&](int s) {
#pragma unroll
        for (int p = 0; p < TI; ++p) {
            const uint32_t hbase = sb + XOFF(s, p) + b_off;
            uint32_t bh[16];
#pragma unroll
            for (int ng = 0; ng < 4; ++ng)
                ldsm4(hbase + (uint32_t)(ng * 16 * XSTRIDE), bh + 4 * ng);
#pragma unroll
            for (int nt = 0; nt < 8; ++nt) {
                const int ng = nt >> 1, t = nt & 1;
                const uint32_t b0 = bh[ng * 4 + t * 2];
                const uint32_t b1 = bh[ng * 4 + t * 2 + 1];
                mma16816(acc[p][nt], ah[p], b0, b1);
                mma16816(acc[p][nt], al[p], b0, b1);
            }
        }
    };

    // ---- prologue ----
    ldg_w(0);
    ldg_x(0, 0);
    ldg_x(1, 1);
    sts_x(0, 0);
    __syncthreads();

    for (int kc = 0; kc < NCHUNK; ++kc) {
        cvt_w();
        if (kc + 1 < NCHUNK) {
            ldg_w(kc + 1);
            sts_x((kc + 1) & (NSTAGE - 1), (kc + 1) & 1);
        }
        if (kc + 2 < NCHUNK)
            ldg_x(kc + 2, kc & 1);
        compute(kc & (NSTAGE - 1));
        if (kc + 1 < NCHUNK)
            __syncthreads();
    }

    // ---- epilogue: float2 stores along i ----
    float* oi = out + i0;
#pragma unroll
    for (int half = 0; half < 2; ++half) {
        const int o = wid * 16 + row0 + half * 8;
        const float bv0 = bias[(size_t)i0 * COUT + o];
        const float bv1 = bias[(size_t)(i0 + 1) * COUT + o];
#pragma unroll
        for (int nt = 0; nt < 8; ++nt) {
#pragma unroll
            for (int cc = 0; cc < 2; ++cc) {
                const int b = nt * 8 + (lane & 3) * 2 + cc;
                const int c = half * 2 + cc;
                float2 v;
                v.x = acc[0][nt][c] + bv0;
                v.y = acc[1][nt][c] + bv1;
                *reinterpret_cast<float2*>(oi + (size_t)(b * COUT + o) * NPOS) = v;
            }
        }
    }
}

extern "C" void kernel_launch(void* const* d_in, const int* in_sizes, int n_in,
                              void* d_out, int out_size) {
    const float* x    = (const float*)d_in[0];
    const float* W    = (const float*)d_in[1];
    const float* bias = (const float*)d_in[2];
    float* out        = (float*)d_out;
    (void)in_sizes; (void)n_in; (void)out_size;

    x_transpose_kernel<<<BATCH * (NPOS / 32), 256>>>(x);
    fc_hmma7_kernel<<<NPOS / TI, THREADS>>>(W, bias, out);
}

// round 10
// speedup vs baseline: 1.1522x; 1.1522x over previous
#include <cuda_runtime.h>
#include <cuda_fp16.h>
#include <cstdint>

#define NPOS    2048
#define CIN     256
#define COUT    256
#define BATCH   64
#define TI      4
#define KC      16
#define NCHUNK  (CIN / KC)     // 16
#define THREADS 512
#define NSTAGE  4

#define XSTRIDE 48
#define XT_BYTES    (BATCH * XSTRIDE)           // 3072 (one pos tile)
#define STAGE_BYTES (TI * XT_BYTES)             // 12288
#define XOFF(s, p) ((s) * STAGE_BYTES + (p) * XT_BYTES)
#define SMEM_BYTES  (NSTAGE * STAGE_BYTES)      // 49152

// scratch: xt[iq(512)][kc(16)][pos(4)][b(64)][kslot(16)] f16
__device__ __half g_xt[(NPOS / TI) * NCHUNK * TI * BATCH * KC];

static __device__ __forceinline__ uint32_t smem_u32(const void* p) {
    uint32_t a;
    asm("{ .reg .u64 t; cvta.to.shared.u64 t, %1; cvt.u32.u64 %0, t; }"
        : "=r"(a) : "l"(p));
    return a;
}

static __device__ __forceinline__ uint32_t h2pack(float lo, float hi) {
    __half2 h = __floats2half2_rn(lo, hi);
    return *reinterpret_cast<uint32_t*>(&h);
}

static __device__ __forceinline__ void sts128(uint32_t addr, uint4 v) {
    asm volatile("st.shared.v4.u32 [%0], {%1, %2, %3, %4};"
                 :: "r"(addr), "r"(v.x), "r"(v.y), "r"(v.z), "r"(v.w) : "memory");
}

static __device__ __forceinline__ void ldsm4(uint32_t addr, uint32_t r[4]) {
    asm volatile("ldmatrix.sync.aligned.m8n8.x4.shared.b16 {%0,%1,%2,%3}, [%4];"
                 : "=r"(r[0]), "=r"(r[1]), "=r"(r[2]), "=r"(r[3]) : "r"(addr));
}

static __device__ __forceinline__ void mma16816(float d[4], const uint32_t a[4],
                                                const uint32_t b0, const uint32_t b1) {
    asm volatile(
        "mma.sync.aligned.m16n8k16.row.col.f32.f16.f16.f32 "
        "{%0,%1,%2,%3}, {%4,%5,%6,%7}, {%8,%9}, {%0,%1,%2,%3};"
        : "+f"(d[0]), "+f"(d[1]), "+f"(d[2]), "+f"(d[3])
        : "r"(a[0]), "r"(a[1]), "r"(a[2]), "r"(a[3]), "r"(b0), "r"(b1));
}

// k permutation: physical k (within chunk) 4c+d -> halfword slot
static __device__ __forceinline__ int kslot(int kappa) {
    const int c = kappa >> 2, d = kappa & 3;
    return (d < 2) ? (2 * c + d) : (2 * c + d + 6);
}

// ============================================================================
// Pass 1: x[b][c][i] f32 -> xt[iq][kc][pos][b][kslot] f16, coalesced both sides.
// CTA = 16 b x 32 i x 128 c. Grid = 4(bg) x 64(ib) x 2(ch) = 512 CTAs.
// smem row per i: 512B = 32 units of 16B, unit swizzled by +5*i (mod 32).
// ============================================================================
__global__ __launch_bounds__(256)
void x_transpose3(const float* __restrict__ x) {
    __shared__ __align__(16) __half st[32 * 256];   // 16 KB

    const int tid = threadIdx.x;
    const int bg  = blockIdx.x >> 7;            // 0..3
    const int ib  = (blockIdx.x >> 1) & 63;     // 0..63
    const int ch  = blockIdx.x & 1;             // 0..1
    const int b0  = bg * 16;
    const int i0  = ib * 32;

    for (int kc = 0; kc < 8; ++kc) {
        const int kcg = ch * 8 + kc;

        // ---- Phase A: coalesced reads, scatter into swizzled smem ----
#pragma unroll
        for (int j = 0; j < 8; ++j) {
            const int u   = tid + j * 256;       // [0,2048)
            const int iq  = u & 7;
            const int c16 = (u >> 3) & 15;
            const int bl  = u >> 7;              // 0..15
            const float4 v = *reinterpret_cast<const float4*>(
                x + ((size_t)((b0 + bl) * CIN + kcg * KC + c16)) * NPOS + i0 + iq * 4);
            const int col  = bl * 16 + kslot(c16);
            const int unit = col >> 3;           // logical 16B unit
            const int inr  = col & 7;
            const float f[4] = {v.x, v.y, v.z, v.w};
#pragma unroll
            for (int e = 0; e < 4; ++e) {
                const int i = iq * 4 + e;
                const int pu = (unit + 5 * i) & 31;
                st[i * 256 + pu * 8 + inr] = __float2half_rn(f[e]);
            }
        }
        __syncthreads();

        // ---- Phase B: warp-contiguous 512B writes per (i, kc) ----
#pragma unroll
        for (int j = 0; j < 4; ++j) {
            const int u    = tid + j * 256;      // [0,1024)
            const int il   = u >> 5;             // 0..31
            const int part = u & 31;             // logical 16B part
            const int gi   = i0 + il;
            const int pu   = (part + 5 * il) & 31;
            const uint4 v = *reinterpret_cast<const uint4*>(&st[il * 256 + pu * 8]);
            const size_t dst = (((size_t)(gi >> 2) * NCHUNK + kcg) * TI + (gi & 3)) * 1024
                             + bg * 256 + part * 8;
            *reinterpret_cast<uint4*>(&g_xt[dst]) = v;
        }
        __syncthreads();
    }
}

// ============================================================================
// Main GEMM: TI=4 positions, M-split across 2 CTAs, exchange epilogue.
// ============================================================================
__global__ __launch_bounds__(THREADS, 1)
void fc_hmma8_kernel(const float* __restrict__ W,     // [N_POS, C_OUT, C_IN]
                     const float* __restrict__ bias,  // [N_POS, C_OUT]
                     float* __restrict__ out)         // [B, C_OUT, N_POS]
{
    __shared__ __align__(128) char xs[SMEM_BYTES];
    const uint32_t sb = smem_u32(xs);

    const int tid  = threadIdx.x;
    const int wid  = tid >> 5;
    const int lane = tid & 31;

    const int ig = blockIdx.x >> 1;          // i-quad group
    const int mh = blockIdx.x & 1;           // M half
    const int i0 = ig * TI;

    const int mg = wid & 7;                  // M group within half (16 rows)
    const int pg = wid >> 3;                 // pos-pair group

    const int row0 = lane >> 2;
    const int kq   = (lane & 3) * 4;

    const float* Wp[2];
#pragma unroll
    for (int lp = 0; lp < 2; ++lp)
        Wp[lp] = W + ((size_t)(i0 + pg * 2 + lp) * COUT + mh * 128 + mg * 16 + row0) * CIN;

    // xt: block for (ig, kc) = 4096 hw; thread's 16B at tid*8
    const __half* xtb = g_xt + (size_t)ig * (NCHUNK * 4096) + tid * 8;

    // smem dest: pos = tid>>7, b = (tid>>1)&63, part = tid&1
    const uint32_t sdst = (uint32_t)XOFF(0, tid >> 7)
                        + (uint32_t)(((tid >> 1) & 63) * XSTRIDE + (tid & 1) * 16);

    float acc[2][8][4];
#pragma unroll
    for (int p = 0; p < 2; ++p)
#pragma unroll
        for (int n = 0; n < 8; ++n)
#pragma unroll
            for (int c = 0; c < 4; ++c) acc[p][n][c] = 0.0f;

    const int bj = lane >> 3, br = lane & 7;
    const uint32_t b_off = (uint32_t)(((bj & 2) * 4 + br) * XSTRIDE + ((bj & 1) << 4));

    float4 q[2][2];
    uint4  xr[2];

    auto ldg_w = [&](int kc) {
        const int kb = kc * KC + kq;
#pragma unroll
        for (int lp = 0; lp < 2; ++lp) {
            q[lp][0] = *reinterpret_cast<const float4*>(Wp[lp] + kb);
            q[lp][1] = *reinterpret_cast<const float4*>(Wp[lp] + 8 * CIN + kb);
        }
    };

    auto ldg_x = [&](int kc, int set) {
        xr[set] = *reinterpret_cast<const uint4*>(xtb + (size_t)kc * 4096);
    };

    auto sts_x = [&](int s, int set) {
        sts128(sb + sdst + (uint32_t)(s * STAGE_BYTES), xr[set]);
    };

    uint32_t ah[2][4], al[2][4];
    auto cvt_w = [&]() {
#pragma unroll
        for (int lp = 0; lp < 2; ++lp) {
#pragma unroll
            for (int r = 0; r < 2; ++r) {
                const float4 v = q[lp][r];
                const uint32_t h02 = h2pack(v.x, v.y);
                const uint32_t h13 = h2pack(v.z, v.w);
                __half2 hh02 = *reinterpret_cast<const __half2*>(&h02);
                __half2 hh13 = *reinterpret_cast<const __half2*>(&h13);
                ah[lp][r]     = h02;
                ah[lp][r + 2] = h13;
                al[lp][r]     = h2pack(v.x - __low2float(hh02), v.y - __high2float(hh02));
                al[lp][r + 2] = h2pack(v.z - __low2float(hh13), v.w - __high2float(hh13));
            }
        }
    };

    auto compute = [&](int s) {
#pragma unroll
        for (int lp = 0; lp < 2; ++lp) {
            const uint32_t hbase = sb + XOFF(s, pg * 2 + lp) + b_off;
            uint32_t bh[16];
#pragma unroll
            for (int ng = 0; ng < 4; ++ng)
                ldsm4(hbase + (uint32_t)(ng * 16 * XSTRIDE), bh + 4 * ng);
#pragma unroll
            for (int nt = 0; nt < 8; ++nt) {
                const int ng = nt >> 1, t = nt & 1;
                const uint32_t b0 = bh[ng * 4 + t * 2];
                const uint32_t b1 = bh[ng * 4 + t * 2 + 1];
                mma16816(acc[lp][nt], ah[lp], b0, b1);
                mma16816(acc[lp][nt], al[lp], b0, b1);
            }
        }
    };

    // ---- prologue ----
    ldg_w(0);
    ldg_x(0, 0);
    ldg_x(1, 1);
    sts_x(0, 0);
    __syncthreads();

    for (int kc = 0; kc < NCHUNK; ++kc) {
        cvt_w();
        if (kc + 1 < NCHUNK) {
            ldg_w(kc + 1);
            sts_x((kc + 1) & (NSTAGE - 1), (kc + 1) & 1);
        }
        if (kc + 2 < NCHUNK)
            ldg_x(kc + 2, kc & 1);
        compute(kc & (NSTAGE - 1));
        if (kc + 1 < NCHUNK)
            __syncthreads();
    }

    // ---- epilogue: pos-pair exchange through smem, float4 stores along i ----
    __syncthreads();
    float2* ep = reinterpret_cast<float2*>(xs);   // [mg(8)][entry(16)][lane(32)]

#pragma unroll
    for (int half = 0; half < 2; ++half) {
        const int o = mh * 128 + mg * 16 + row0 + half * 8;
        const float bvA = bias[(size_t)(i0 + pg * 2 + 0) * COUT + o];
        const float bvB = bias[(size_t)(i0 + pg * 2 + 1) * COUT + o];

        if (pg == 0) {
#pragma unroll
            for (int nt = 0; nt < 8; ++nt)
#pragma unroll
                for (int cc = 0; cc < 2; ++cc) {
                    const int e = nt * 2 + cc;
                    float2 v;
                    v.x = acc[0][nt][half * 2 + cc] + bvA;
                    v.y = acc[1][nt][half * 2 + cc] + bvB;
                    ep[(mg * 16 + e) * 32 + lane] = v;
                }
        }
        __syncthreads();
        if (pg == 1) {
#pragma unroll
            for (int nt = 0; nt < 8; ++nt)
#pragma unroll
                for (int cc = 0; cc < 2; ++cc) {
                    const int e = nt * 2 + cc;
                    const float2 v01 = ep[(mg * 16 + e) * 32 + lane];
                    float4 v;
                    v.x = v01.x;
                    v.y = v01.y;
                    v.z = acc[0][nt][half * 2 + cc] + bvA;
                    v.w = acc[1][nt][half * 2 + cc] + bvB;
                    const int b = nt * 8 + (lane & 3) * 2 + cc;
                    *reinterpret_cast<float4*>(out + (size_t)(b * COUT + o) * NPOS + i0) = v;
                }
        }
        __syncthreads();
    }
}

extern "C" void kernel_launch(void* const* d_in, const int* in_sizes, int n_in,
                              void* d_out, int out_size) {
    const float* x    = (const float*)d_in[0];
    const float* W    = (const float*)d_in[1];
    const float* bias = (const float*)d_in[2];
    float* out        = (float*)d_out;
    (void)in_sizes; (void)n_in; (void)out_size;

    x_transpose3<<<512, 256>>>(x);
    fc_hmma8_kernel<<<(NPOS / TI) * 2, THREADS>>>(W, bias, out);
}

// round 11
// speedup vs baseline: 1.2041x; 1.0450x over previous
#include <cuda_runtime.h>
#include <cuda_fp16.h>
#include <cstdint>

#define NPOS    2048
#define CIN     256
#define COUT    256
#define BATCH   64
#define TI      4
#define KC      16
#define NCHUNK  (CIN / KC)     // 16
#define THREADS 256
#define NSTAGE  4

#define XSTRIDE 48
#define XT_BYTES    (BATCH * XSTRIDE)           // 3072 (one pos tile)
#define STAGE_BYTES (TI * XT_BYTES)             // 12288
#define XOFF(s, p) ((s) * STAGE_BYTES + (p) * XT_BYTES)
#define SMEM_BYTES  (NSTAGE * STAGE_BYTES)      // 49152 (48KB)

// scratch: xt[iq(512)][kc(16)][pos(4)][b(64)][kslot(16)] f16
__device__ __half g_xt[(NPOS / TI) * NCHUNK * TI * BATCH * KC];

static __device__ __forceinline__ uint32_t smem_u32(const void* p) {
    uint32_t a;
    asm("{ .reg .u64 t; cvta.to.shared.u64 t, %1; cvt.u32.u64 %0, t; }"
        : "=r"(a) : "l"(p));
    return a;
}

static __device__ __forceinline__ uint32_t h2pack(float lo, float hi) {
    __half2 h = __floats2half2_rn(lo, hi);
    return *reinterpret_cast<uint32_t*>(&h);
}

static __device__ __forceinline__ void sts128(uint32_t addr, uint4 v) {
    asm volatile("st.shared.v4.u32 [%0], {%1, %2, %3, %4};"
                 :: "r"(addr), "r"(v.x), "r"(v.y), "r"(v.z), "r"(v.w) : "memory");
}

static __device__ __forceinline__ void ldsm4(uint32_t addr, uint32_t r[4]) {
    asm volatile("ldmatrix.sync.aligned.m8n8.x4.shared.b16 {%0,%1,%2,%3}, [%4];"
                 : "=r"(r[0]), "=r"(r[1]), "=r"(r[2]), "=r"(r[3]) : "r"(addr));
}

static __device__ __forceinline__ void mma16816(float d[4], const uint32_t a[4],
                                                const uint32_t b0, const uint32_t b1) {
    asm volatile(
        "mma.sync.aligned.m16n8k16.row.col.f32.f16.f16.f32 "
        "{%0,%1,%2,%3}, {%4,%5,%6,%7}, {%8,%9}, {%0,%1,%2,%3};"
        : "+f"(d[0]), "+f"(d[1]), "+f"(d[2]), "+f"(d[3])
        : "r"(a[0]), "r"(a[1]), "r"(a[2]), "r"(a[3]), "r"(b0), "r"(b1));
}

// k permutation: physical k (within chunk) 4c+d -> halfword slot
static __device__ __forceinline__ int kslot(int kappa) {
    const int c = kappa >> 2, d = kappa & 3;
    return (d < 2) ? (2 * c + d) : (2 * c + d + 6);
}

// ============================================================================
// Pass 1: x[b][c][i] f32 -> xt[iq][kc][pos][b][kslot] f16, coalesced both sides.
// CTA = 16 b x 32 i x 64 c (4 kc). Grid = 4(bg) x 64(ib) x 4(ch) = 1024 CTAs.
// ============================================================================
__global__ __launch_bounds__(256)
void x_transpose4(const float* __restrict__ x) {
    __shared__ __align__(16) __half st[32 * 256];   // 16 KB

    const int tid = threadIdx.x;
    const int bg  = blockIdx.x >> 8;            // 0..3
    const int ib  = (blockIdx.x >> 2) & 63;     // 0..63
    const int ch  = blockIdx.x & 3;             // 0..3
    const int b0  = bg * 16;
    const int i0  = ib * 32;

    for (int kc = 0; kc < 4; ++kc) {
        const int kcg = ch * 4 + kc;

        // ---- Phase A: coalesced reads, scatter into swizzled smem ----
#pragma unroll
        for (int j = 0; j < 8; ++j) {
            const int u   = tid + j * 256;       // [0,2048)
            const int iq  = u & 7;
            const int c16 = (u >> 3) & 15;
            const int bl  = u >> 7;              // 0..15
            const float4 v = *reinterpret_cast<const float4*>(
                x + ((size_t)((b0 + bl) * CIN + kcg * KC + c16)) * NPOS + i0 + iq * 4);
            const int col  = bl * 16 + kslot(c16);
            const int unit = col >> 3;
            const int inr  = col & 7;
            const float f[4] = {v.x, v.y, v.z, v.w};
#pragma unroll
            for (int e = 0; e < 4; ++e) {
                const int i = iq * 4 + e;
                const int pu = (unit + 5 * i) & 31;
                st[i * 256 + pu * 8 + inr] = __float2half_rn(f[e]);
            }
        }
        __syncthreads();

        // ---- Phase B: warp-contiguous 512B writes per (i, kc) ----
#pragma unroll
        for (int j = 0; j < 4; ++j) {
            const int u    = tid + j * 256;      // [0,1024)
            const int il   = u >> 5;
            const int part = u & 31;
            const int gi   = i0 + il;
            const int pu   = (part + 5 * il) & 31;
            const uint4 v = *reinterpret_cast<const uint4*>(&st[il * 256 + pu * 8]);
            const size_t dst = (((size_t)(gi >> 2) * NCHUNK + kcg) * TI + (gi & 3)) * 1024
                             + bg * 256 + part * 8;
            *reinterpret_cast<uint4*>(&g_xt[dst]) = v;
        }
        __syncthreads();
    }
}

// ============================================================================
// Main GEMM: 256-thread CTAs (2/SM), TI=4, M-quarter split, exchange epilogue.
// ============================================================================
__global__ __launch_bounds__(THREADS, 2)
void fc_hmma9_kernel(const float* __restrict__ W,     // [N_POS, C_OUT, C_IN]
                     const float* __restrict__ bias,  // [N_POS, C_OUT]
                     float* __restrict__ out)         // [B, C_OUT, N_POS]
{
    __shared__ __align__(128) char xs[SMEM_BYTES];
    const uint32_t sb = smem_u32(xs);

    const int tid  = threadIdx.x;
    const int wid  = tid >> 5;               // 8 warps
    const int lane = tid & 31;

    const int ig = blockIdx.x >> 2;          // i-quad group
    const int mq = blockIdx.x & 3;           // M quarter (64 rows)
    const int i0 = ig * TI;

    const int mg = wid & 3;                  // M group within quarter (16 rows)
    const int pg = wid >> 2;                 // pos-pair group

    const int row0 = lane >> 2;
    const int kq   = (lane & 3) * 4;

    const float* Wp[2];
#pragma unroll
    for (int lp = 0; lp < 2; ++lp)
        Wp[lp] = W + ((size_t)(i0 + pg * 2 + lp) * COUT + mq * 64 + mg * 16 + row0) * CIN;

    // xt: block for (ig, kc) = 4096 hw = 8KB; thread covers 2 x 16B units
    const __half* xtb = g_xt + (size_t)ig * (NCHUNK * 4096) + tid * 8;

    // smem dest for unit u: pos = u>>7, b = (u>>1)&63, part = u&1
    uint32_t sdst[2];
#pragma unroll
    for (int v = 0; v < 2; ++v) {
        const int u = tid + v * THREADS;      // [0,512)
        sdst[v] = (uint32_t)XOFF(0, u >> 7)
                + (uint32_t)(((u >> 1) & 63) * XSTRIDE + (u & 1) * 16);
    }

    float acc[2][8][4];
#pragma unroll
    for (int p = 0; p < 2; ++p)
#pragma unroll
        for (int n = 0; n < 8; ++n)
#pragma unroll
            for (int c = 0; c < 4; ++c) acc[p][n][c] = 0.0f;

    const int bj = lane >> 3, br = lane & 7;
    const uint32_t b_off = (uint32_t)(((bj & 2) * 4 + br) * XSTRIDE + ((bj & 1) << 4));

    float4 q[2][2];
    uint4  xr[2][2];        // [set][unit]

    auto ldg_w = [&](int kc) {
        const int kb = kc * KC + kq;
#pragma unroll
        for (int lp = 0; lp < 2; ++lp) {
            q[lp][0] = *reinterpret_cast<const float4*>(Wp[lp] + kb);
            q[lp][1] = *reinterpret_cast<const float4*>(Wp[lp] + 8 * CIN + kb);
        }
    };

    auto ldg_x = [&](int kc, int set) {
        const __half* p = xtb + (size_t)kc * 4096;
        xr[set][0] = *reinterpret_cast<const uint4*>(p);
        xr[set][1] = *reinterpret_cast<const uint4*>(p + THREADS * 8);
    };

    auto sts_x = [&](int s, int set) {
        sts128(sb + sdst[0] + (uint32_t)(s * STAGE_BYTES), xr[set][0]);
        sts128(sb + sdst[1] + (uint32_t)(s * STAGE_BYTES), xr[set][1]);
    };

    uint32_t ah[2][4], al[2][4];
    auto cvt_w = [&]() {
#pragma unroll
        for (int lp = 0; lp < 2; ++lp) {
#pragma unroll
            for (int r = 0; r < 2; ++r) {
                const float4 v = q[lp][r];
                const uint32_t h02 = h2pack(v.x, v.y);
                const uint32_t h13 = h2pack(v.z, v.w);
                __half2 hh02 = *reinterpret_cast<const __half2*>(&h02);
                __half2 hh13 = *reinterpret_cast<const __half2*>(&h13);
                ah[lp][r]     = h02;
                ah[lp][r + 2] = h13;
                al[lp][r]     = h2pack(v.x - __low2float(hh02), v.y - __high2float(hh02));
                al[lp][r + 2] = h2pack(v.z - __low2float(hh13), v.w - __high2float(hh13));
            }
        }
    };

    auto compute = [&](int s) {
#pragma unroll
        for (int lp = 0; lp < 2; ++lp) {
            const uint32_t hbase = sb + XOFF(s, pg * 2 + lp) + b_off;
            uint32_t bh[16];
#pragma unroll
            for (int ng = 0; ng < 4; ++ng)
                ldsm4(hbase + (uint32_t)(ng * 16 * XSTRIDE), bh + 4 * ng);
#pragma unroll
            for (int nt = 0; nt < 8; ++nt) {
                const int ng = nt >> 1, t = nt & 1;
                const uint32_t b0 = bh[ng * 4 + t * 2];
                const uint32_t b1 = bh[ng * 4 + t * 2 + 1];
                mma16816(acc[lp][nt], ah[lp], b0, b1);
                mma16816(acc[lp][nt], al[lp], b0, b1);
            }
        }
    };

    // ---- prologue ----
    ldg_w(0);
    ldg_x(0, 0);
    ldg_x(1, 1);
    sts_x(0, 0);
    __syncthreads();

    for (int kc = 0; kc < NCHUNK; ++kc) {
        cvt_w();
        if (kc + 1 < NCHUNK) {
            ldg_w(kc + 1);
            sts_x((kc + 1) & (NSTAGE - 1), (kc + 1) & 1);
        }
        if (kc + 2 < NCHUNK)
            ldg_x(kc + 2, kc & 1);
        compute(kc & (NSTAGE - 1));
        if (kc + 1 < NCHUNK)
            __syncthreads();
    }

    // ---- epilogue: pos-pair exchange through smem, float4 stores along i ----
    __syncthreads();
    float2* ep = reinterpret_cast<float2*>(xs);   // [mg(4)][entry(16)][lane(32)]

#pragma unroll
    for (int half = 0; half < 2; ++half) {
        const int o = mq * 64 + mg * 16 + row0 + half * 8;
        const float bvA = bias[(size_t)(i0 + pg * 2 + 0) * COUT + o];
        const float bvB = bias[(size_t)(i0 + pg * 2 + 1) * COUT + o];

        if (pg == 0) {
#pragma unroll
            for (int nt = 0; nt < 8; ++nt)
#pragma unroll
                for (int cc = 0; cc < 2; ++cc) {
                    const int e = nt * 2 + cc;
                    float2 v;
                    v.x = acc[0][nt][half * 2 + cc] + bvA;
                    v.y = acc[1][nt][half * 2 + cc] + bvB;
                    ep[(mg * 16 + e) * 32 + lane] = v;
                }
        }
        __syncthreads();
        if (pg == 1) {
#pragma unroll
            for (int nt = 0; nt < 8; ++nt)
#pragma unroll
                for (int cc = 0; cc < 2; ++cc) {
                    const int e = nt * 2 + cc;
                    const float2 v01 = ep[(mg * 16 + e) * 32 + lane];
                    float4 v;
                    v.x = v01.x;
                    v.y = v01.y;
                    v.z = acc[0][nt][half * 2 + cc] + bvA;
                    v.w = acc[1][nt][half * 2 + cc] + bvB;
                    const int b = nt * 8 + (lane & 3) * 2 + cc;
                    *reinterpret_cast<float4*>(out + (size_t)(b * COUT + o) * NPOS + i0) = v;
                }
        }
        __syncthreads();
    }
}

extern "C" void kernel_launch(void* const* d_in, const int* in_sizes, int n_in,
                              void* d_out, int out_size) {
    const float* x    = (const float*)d_in[0];
    const float* W    = (const float*)d_in[1];
    const float* bias = (const float*)d_in[2];
    float* out        = (float*)d_out;
    (void)in_sizes; (void)n_in; (void)out_size;

    x_transpose4<<<1024, 256>>>(x);
    fc_hmma9_kernel<<<(NPOS / TI) * 4, THREADS>>>(W, bias, out);
}

// round 12
// speedup vs baseline: 1.2416x; 1.0311x over previous
#include <cuda_runtime.h>
#include <cuda_fp16.h>
#include <cstdint>

#define NPOS    2048
#define CIN     256
#define COUT    256
#define BATCH   64
#define TI      4
#define KC      16
#define NCHUNK  (CIN / KC)     // 16
#define THREADS 256
#define NSTAGE  4

#define XSTRIDE 48
#define XT_BYTES    (BATCH * XSTRIDE)           // 3072 (one pos tile)
#define STAGE_BYTES (TI * XT_BYTES)             // 12288
#define XOFF(s, p) ((s) * STAGE_BYTES + (p) * XT_BYTES)
#define SMEM_BYTES  (NSTAGE * STAGE_BYTES)      // 49152

// scratch: xt[iq(512)][kc(16)][pos(4)][b(64)][kslot(16)] f16
__device__ __half g_xt[(NPOS / TI) * NCHUNK * TI * BATCH * KC];

static __device__ __forceinline__ uint32_t smem_u32(const void* p) {
    uint32_t a;
    asm("{ .reg .u64 t; cvta.to.shared.u64 t, %1; cvt.u32.u64 %0, t; }"
        : "=r"(a) : "l"(p));
    return a;
}

static __device__ __forceinline__ uint32_t h2pack(float lo, float hi) {
    __half2 h = __floats2half2_rn(lo, hi);
    return *reinterpret_cast<uint32_t*>(&h);
}

static __device__ __forceinline__ void sts128(uint32_t addr, uint4 v) {
    asm volatile("st.shared.v4.u32 [%0], {%1, %2, %3, %4};"
                 :: "r"(addr), "r"(v.x), "r"(v.y), "r"(v.z), "r"(v.w) : "memory");
}

static __device__ __forceinline__ void ldsm4(uint32_t addr, uint32_t r[4]) {
    asm volatile("ldmatrix.sync.aligned.m8n8.x4.shared.b16 {%0,%1,%2,%3}, [%4];"
                 : "=r"(r[0]), "=r"(r[1]), "=r"(r[2]), "=r"(r[3]) : "r"(addr));
}

static __device__ __forceinline__ void mma16816(float d[4], const uint32_t a[4],
                                                const uint32_t b0, const uint32_t b1) {
    asm volatile(
        "mma.sync.aligned.m16n8k16.row.col.f32.f16.f16.f32 "
        "{%0,%1,%2,%3}, {%4,%5,%6,%7}, {%8,%9}, {%0,%1,%2,%3};"
        : "+f"(d[0]), "+f"(d[1]), "+f"(d[2]), "+f"(d[3])
        : "r"(a[0]), "r"(a[1]), "r"(a[2]), "r"(a[3]), "r"(b0), "r"(b1));
}

// k permutation: physical k (within chunk) 4c+d -> halfword slot
static __device__ __forceinline__ int kslot(int kappa) {
    const int c = kappa >> 2, d = kappa & 3;
    return (d < 2) ? (2 * c + d) : (2 * c + d + 6);
}

// ============================================================================
// Pass 1: x[b][c][i] f32 -> xt[iq][kc][pos][b][kslot] f16.
// half2-packed STS (even-kappa pairs are slot-adjacent) + i-aware swizzle.
// CTA = 16 b x 32 i x 64 c (4 kc). Grid = 1024.
// ============================================================================
__global__ __launch_bounds__(256)
void x_transpose5(const float* __restrict__ x) {
    __shared__ __align__(16) __half st[32 * 256];   // 16 KB

    const int tid = threadIdx.x;
    const int bg  = blockIdx.x >> 8;            // 0..3
    const int ib  = (blockIdx.x >> 2) & 63;     // 0..63
    const int ch  = blockIdx.x & 3;             // 0..3
    const int b0  = bg * 16;
    const int i0  = ib * 32;

    for (int kc = 0; kc < 4; ++kc) {
        const int kcg = ch * 4 + kc;

        // ---- Phase A: coalesced reads, half2 STS into swizzled smem ----
#pragma unroll
        for (int j = 0; j < 4; ++j) {
            const int u  = tid + j * 256;        // [0,1024)
            const int iq = u & 7;
            const int kp = (u >> 3) & 7;         // kappa pair = 2*kp
            const int bl = u >> 6;               // 0..15
            const float* base = x + ((size_t)((b0 + bl) * CIN + kcg * KC + 2 * kp)) * NPOS
                                  + i0 + iq * 4;
            const float4 v0 = *reinterpret_cast<const float4*>(base);
            const float4 v1 = *reinterpret_cast<const float4*>(base + NPOS);
            const int s0   = kslot(2 * kp);      // even
            const int col  = bl * 16 + s0;
            const int unit = col >> 3;
            const int inr  = col & 7;            // even
            const float a[4] = {v0.x, v0.y, v0.z, v0.w};
            const float b[4] = {v1.x, v1.y, v1.z, v1.w};
#pragma unroll
            for (int e = 0; e < 4; ++e) {
                const int i  = iq * 4 + e;
                const int pu = (unit + i + (i >> 2)) & 31;
                *reinterpret_cast<__half2*>(&st[i * 256 + pu * 8 + inr]) =
                    __floats2half2_rn(a[e], b[e]);
            }
        }
        __syncthreads();

        // ---- Phase B: warp-contiguous 512B writes per (i, kc) ----
#pragma unroll
        for (int j = 0; j < 4; ++j) {
            const int u    = tid + j * 256;      // [0,1024)
            const int il   = u >> 5;
            const int part = u & 31;
            const int gi   = i0 + il;
            const int pu   = (part + il + (il >> 2)) & 31;
            const uint4 v = *reinterpret_cast<const uint4*>(&st[il * 256 + pu * 8]);
            const size_t dst = (((size_t)(gi >> 2) * NCHUNK + kcg) * TI + (gi & 3)) * 1024
                             + bg * 256 + part * 8;
            *reinterpret_cast<uint4*>(&g_xt[dst]) = v;
        }
        __syncthreads();
    }
}

// ============================================================================
// Main GEMM: 256-thread CTAs (2/SM), TI=4, M-quarter split, W hi-only f16.
// ============================================================================
__global__ __launch_bounds__(THREADS, 2)
void fc_hmma10_kernel(const float* __restrict__ W,     // [N_POS, C_OUT, C_IN]
                      const float* __restrict__ bias,  // [N_POS, C_OUT]
                      float* __restrict__ out)         // [B, C_OUT, N_POS]
{
    __shared__ __align__(128) char xs[SMEM_BYTES];
    const uint32_t sb = smem_u32(xs);

    const int tid  = threadIdx.x;
    const int wid  = tid >> 5;               // 8 warps
    const int lane = tid & 31;

    const int ig = blockIdx.x >> 2;          // i-quad group
    const int mq = blockIdx.x & 3;           // M quarter (64 rows)
    const int i0 = ig * TI;

    const int mg = wid & 3;                  // M group within quarter (16 rows)
    const int pg = wid >> 2;                 // pos-pair group

    const int row0 = lane >> 2;
    const int kq   = (lane & 3) * 4;

    const float* Wp[2];
#pragma unroll
    for (int lp = 0; lp < 2; ++lp)
        Wp[lp] = W + ((size_t)(i0 + pg * 2 + lp) * COUT + mq * 64 + mg * 16 + row0) * CIN;

    const __half* xtb = g_xt + (size_t)ig * (NCHUNK * 4096) + tid * 8;

    uint32_t sdst[2];
#pragma unroll
    for (int v = 0; v < 2; ++v) {
        const int u = tid + v * THREADS;      // [0,512)
        sdst[v] = (uint32_t)XOFF(0, u >> 7)
                + (uint32_t)(((u >> 1) & 63) * XSTRIDE + (u & 1) * 16);
    }

    float acc[2][8][4];
#pragma unroll
    for (int p = 0; p < 2; ++p)
#pragma unroll
        for (int n = 0; n < 8; ++n)
#pragma unroll
            for (int c = 0; c < 4; ++c) acc[p][n][c] = 0.0f;

    const int bj = lane >> 3, br = lane & 7;
    const uint32_t b_off = (uint32_t)(((bj & 2) * 4 + br) * XSTRIDE + ((bj & 1) << 4));

    float4 q[2][2];
    uint4  xr[2][2];

    auto ldg_w = [&](int kc) {
        const int kb = kc * KC + kq;
#pragma unroll
        for (int lp = 0; lp < 2; ++lp) {
            q[lp][0] = *reinterpret_cast<const float4*>(Wp[lp] + kb);
            q[lp][1] = *reinterpret_cast<const float4*>(Wp[lp] + 8 * CIN + kb);
        }
    };

    auto ldg_x = [&](int kc, int set) {
        const __half* p = xtb + (size_t)kc * 4096;
        xr[set][0] = *reinterpret_cast<const uint4*>(p);
        xr[set][1] = *reinterpret_cast<const uint4*>(p + THREADS * 8);
    };

    auto sts_x = [&](int s, int set) {
        sts128(sb + sdst[0] + (uint32_t)(s * STAGE_BYTES), xr[set][0]);
        sts128(sb + sdst[1] + (uint32_t)(s * STAGE_BYTES), xr[set][1]);
    };

    uint32_t ah[2][4];
    auto cvt_w = [&]() {
#pragma unroll
        for (int lp = 0; lp < 2; ++lp) {
#pragma unroll
            for (int r = 0; r < 2; ++r) {
                const float4 v = q[lp][r];
                ah[lp][r]     = h2pack(v.x, v.y);
                ah[lp][r + 2] = h2pack(v.z, v.w);
            }
        }
    };

    auto compute = [&](int s) {
#pragma unroll
        for (int lp = 0; lp < 2; ++lp) {
            const uint32_t hbase = sb + XOFF(s, pg * 2 + lp) + b_off;
            uint32_t bh[16];
#pragma unroll
            for (int ng = 0; ng < 4; ++ng)
                ldsm4(hbase + (uint32_t)(ng * 16 * XSTRIDE), bh + 4 * ng);
#pragma unroll
            for (int nt = 0; nt < 8; ++nt) {
                const int ng = nt >> 1, t = nt & 1;
                mma16816(acc[lp][nt], ah[lp], bh[ng * 4 + t * 2], bh[ng * 4 + t * 2 + 1]);
            }
        }
    };

    // ---- prologue ----
    ldg_w(0);
    ldg_x(0, 0);
    ldg_x(1, 1);
    sts_x(0, 0);
    __syncthreads();

    for (int kc = 0; kc < NCHUNK; ++kc) {
        cvt_w();
        if (kc + 1 < NCHUNK) {
            ldg_w(kc + 1);
            sts_x((kc + 1) & (NSTAGE - 1), (kc + 1) & 1);
        }
        if (kc + 2 < NCHUNK)
            ldg_x(kc + 2, kc & 1);
        compute(kc & (NSTAGE - 1));
        if (kc + 1 < NCHUNK)
            __syncthreads();
    }

    // ---- epilogue: pos-pair exchange through smem, float4 stores along i ----
    __syncthreads();
    float2* ep = reinterpret_cast<float2*>(xs);

#pragma unroll
    for (int half = 0; half < 2; ++half) {
        const int o = mq * 64 + mg * 16 + row0 + half * 8;
        const float bvA = bias[(size_t)(i0 + pg * 2 + 0) * COUT + o];
        const float bvB = bias[(size_t)(i0 + pg * 2 + 1) * COUT + o];

        if (pg == 0) {
#pragma unroll
            for (int nt = 0; nt < 8; ++nt)
#pragma unroll
                for (int cc = 0; cc < 2; ++cc) {
                    const int e = nt * 2 + cc;
                    float2 v;
                    v.x = acc[0][nt][half * 2 + cc] + bvA;
                    v.y = acc[1][nt][half * 2 + cc] + bvB;
                    ep[(mg * 16 + e) * 32 + lane] = v;
                }
        }
        __syncthreads();
        if (pg == 1) {
#pragma unroll
            for (int nt = 0; nt < 8; ++nt)
#pragma unroll
                for (int cc = 0; cc < 2; ++cc) {
                    const int e = nt * 2 + cc;
                    const float2 v01 = ep[(mg * 16 + e) * 32 + lane];
                    float4 v;
                    v.x = v01.x;
                    v.y = v01.y;
                    v.z = acc[0][nt][half * 2 + cc] + bvA;
                    v.w = acc[1][nt][half * 2 + cc] + bvB;
                    const int b = nt * 8 + (lane & 3) * 2 + cc;
                    *reinterpret_cast<float4*>(out + (size_t)(b * COUT + o) * NPOS + i0) = v;
                }
        }
        __syncthreads();
    }
}

extern "C" void kernel_launch(void* const* d_in, const int* in_sizes, int n_in,
                              void* d_out, int out_size) {
    const float* x    = (const float*)d_in[0];
    const float* W    = (const float*)d_in[1];
    const float* bias = (const float*)d_in[2];
    float* out        = (float*)d_out;
    (void)in_sizes; (void)n_in; (void)out_size;

    x_transpose5<<<1024, 256>>>(x);
    fc_hmma10_kernel<<<(NPOS / TI) * 4, THREADS>>>(W, bias, out);
}